// round 1
// baseline (speedup 1.0000x reference)
#include <cuda_runtime.h>
#include <cuda_bf16.h>
#include <cstdint>

// Problem constants (fixed by setup_inputs)
#define BB 32
#define NN 2048
#define DD 512
#define EE 512
#define VV 32000
#define TT 32          // output_len
#define NSTEP 31       // T-1 decode steps

// ---------------- scratch (device globals; no allocation allowed) -----------
__device__ float g_h[BB * DD];
__device__ float g_c[BB * DD];
__device__ float g_gates[BB * 4 * DD];
__device__ float g_Hall[NSTEP * BB * DD];     // all h_t
__device__ float g_HW[NSTEP * BB * DD];       // h_t @ W_att^T
__device__ float g_scores[NSTEP * BB * NN];   // 8.1 MB
__device__ float g_h0part[4 * BB * DD];
__device__ float g_cntpad[BB];
__device__ float g_cntptr[BB];
__device__ int   g_mask_mode;                 // 0=byte, 1=int32, 2=float32

// ---------------- mask accessor (dtype detected at runtime) -----------------
__device__ __forceinline__ bool getmask(const void* p, int idx) {
    int m = g_mask_mode;
    if (m == 1) return ((const int*)p)[idx] != 0;
    if (m == 2) return ((const float*)p)[idx] != 0.0f;
    return ((const unsigned char*)p)[idx] != 0;
}

__device__ __forceinline__ float sigm(float x) { return 1.0f / (1.0f + expf(-x)); }

// ---------------- kernels ---------------------------------------------------

__global__ void detect_kernel(const int* pad_as_int) {
    int v = pad_as_int[0];
    g_mask_mode = (v == 1) ? 1 : ((v == 0x3F800000) ? 2 : 0);
}

__global__ void zero_kernel(float4* out, int n4) {
    int idx = blockIdx.x * blockDim.x + threadIdx.x;
    int stride = gridDim.x * blockDim.x;
    float4 z = {0.f, 0.f, 0.f, 0.f};
    for (int i = idx; i < n4; i += stride) out[i] = z;
}

__global__ void sos_kernel(float* out, const int* sosp) {
    int b = threadIdx.x;
    if (b < BB) out[(size_t)b * VV + sosp[0]] = 1.0f;
}

__global__ void counts_kernel(const void* pad, const void* ptr) {
    int b = blockIdx.x, tid = threadIdx.x;
    __shared__ int r1[256], r2[256];
    int c1 = 0, c2 = 0;
    for (int n = tid; n < NN; n += 256) {
        c1 += getmask(pad, b * NN + n) ? 1 : 0;
        c2 += getmask(ptr, b * NN + n) ? 1 : 0;
    }
    r1[tid] = c1; r2[tid] = c2; __syncthreads();
    for (int s = 128; s > 0; s >>= 1) {
        if (tid < s) { r1[tid] += r1[tid + s]; r2[tid] += r2[tid + s]; }
        __syncthreads();
    }
    if (tid == 0) { g_cntpad[b] = (float)r1[0]; g_cntptr[b] = (float)r2[0]; }
}

// h0 partial sums: grid (2 d-chunks, B, 4 n-splits), 256 threads
__global__ void h0part_kernel(const float* __restrict__ enc, const void* pad) {
    int dc = blockIdx.x, b = blockIdx.y, z = blockIdx.z;
    int d = dc * 256 + threadIdx.x;
    float acc = 0.0f;
    int n0 = z * (NN / 4);
    for (int n = n0; n < n0 + NN / 4; n++) {
        if (getmask(pad, b * NN + n))
            acc += enc[((size_t)(b * NN + n)) * DD + d];
    }
    g_h0part[((z * BB) + b) * DD + d] = acc;
}

__global__ void h0fin_kernel() {
    int b = blockIdx.x, d = threadIdx.x;  // 512 threads
    float s = 0.0f;
    #pragma unroll
    for (int z = 0; z < 4; z++) s += g_h0part[((z * BB) + b) * DD + d];
    float h = s / g_cntpad[b];
    g_h[b * DD + d] = h;
    g_c[b * DD + d] = h;
}

// gates[b, j] = b_ih[j]+b_hh[j] + x[b]·W_ih[j,:] + h[b]·W_hh[j,:]
// grid 64 blocks (32 gate rows each), 256 threads
__global__ void gates_kernel(const float* __restrict__ emb,
                             const float* __restrict__ W_ih,
                             const float* __restrict__ W_hh,
                             const float* __restrict__ b_ih,
                             const float* __restrict__ b_hh,
                             const int* __restrict__ target,
                             const int* __restrict__ sosp,
                             int t) {
    __shared__ float Ws[32][33];
    __shared__ float Xs[32][33];
    __shared__ int   toks[32];
    int tid = threadIdx.x;
    int jbase = blockIdx.x * 32;
    if (tid < 32) toks[tid] = (t == 0) ? sosp[0] : target[t * BB + tid];
    __syncthreads();
    int tx = tid & 31;   // batch
    int ty = tid >> 5;   // 0..7
    float acc[4];
    #pragma unroll
    for (int i = 0; i < 4; i++) {
        int j = jbase + ty + 8 * i;
        acc[i] = b_ih[j] + b_hh[j];
    }
    for (int phase = 0; phase < 2; phase++) {
        const float* W = phase ? W_hh : W_ih;
        for (int k0 = 0; k0 < 512; k0 += 32) {
            #pragma unroll
            for (int i = 0; i < 4; i++) {
                int lin = tid + 256 * i;
                int r = lin >> 5, c = lin & 31;
                Ws[r][c] = W[(size_t)(jbase + r) * 512 + k0 + c];
                Xs[r][c] = phase ? g_h[r * DD + k0 + c]
                                 : emb[(size_t)toks[r] * EE + k0 + c];
            }
            __syncthreads();
            #pragma unroll
            for (int kk = 0; kk < 32; kk++) {
                float xv = Xs[tx][kk];
                #pragma unroll
                for (int i = 0; i < 4; i++)
                    acc[i] += Ws[ty + 8 * i][kk] * xv;
            }
            __syncthreads();
        }
    }
    #pragma unroll
    for (int i = 0; i < 4; i++)
        g_gates[tx * (4 * DD) + jbase + ty + 8 * i] = acc[i];
}

// pointwise LSTM: grid B, 512 threads
__global__ void point_kernel(int t) {
    int b = blockIdx.x, d = threadIdx.x;
    const float* g = g_gates + b * (4 * DD);
    float gi = g[d], gf = g[DD + d], gg = g[2 * DD + d], go = g[3 * DD + d];
    float c = g_c[b * DD + d];
    float cn = sigm(gf) * c + sigm(gi) * tanhf(gg);
    float hn = sigm(go) * tanhf(cn);
    g_c[b * DD + d] = cn;
    g_h[b * DD + d] = hn;
    g_Hall[((size_t)t * BB + b) * DD + d] = hn;
}

// HW[m, dout] = Hall[m,:] · W_att[dout,:]   (m = t*B+b), grid (31, 16)
__global__ void hw_kernel(const float* __restrict__ Watt) {
    __shared__ float As[32][33], Bs[32][33];
    int tid = threadIdx.x;
    int mbase = blockIdx.x * 32, nbase = blockIdx.y * 32;
    int tx = tid & 31, ty = tid >> 5;
    float acc[4] = {0.f, 0.f, 0.f, 0.f};
    for (int k0 = 0; k0 < 512; k0 += 32) {
        #pragma unroll
        for (int i = 0; i < 4; i++) {
            int lin = tid + 256 * i;
            int r = lin >> 5, c = lin & 31;
            As[r][c] = g_Hall[(size_t)(mbase + r) * DD + k0 + c];
            Bs[r][c] = Watt[(size_t)(nbase + r) * DD + k0 + c];
        }
        __syncthreads();
        #pragma unroll
        for (int kk = 0; kk < 32; kk++) {
            float av = As[tx][kk];
            #pragma unroll
            for (int i = 0; i < 4; i++) acc[i] += Bs[ty + 8 * i][kk] * av;
        }
        __syncthreads();
    }
    #pragma unroll
    for (int i = 0; i < 4; i++)
        g_HW[(size_t)(mbase + tx) * DD + nbase + ty + 8 * i] = acc[i];
}

// scores[t,b,n] = enc[b,n,:] · HW[t*B+b,:]; grid (32 node tiles, 32 b), 256 thr
__global__ void scores_kernel(const float* __restrict__ enc) {
    __shared__ float Es[64][33];
    __shared__ float Hs[32][33];
    int tid = threadIdx.x;
    int nbase = blockIdx.x * 64;
    int b = blockIdx.y;
    int nn = tid & 63, tg = tid >> 6;   // tg: 0..3, 8 t's each
    float acc[8];
    #pragma unroll
    for (int j = 0; j < 8; j++) acc[j] = 0.f;
    for (int k0 = 0; k0 < 512; k0 += 32) {
        #pragma unroll
        for (int i = 0; i < 8; i++) {
            int lin = tid + 256 * i;
            int r = lin >> 5, c = lin & 31;
            Es[r][c] = enc[((size_t)(b * NN + nbase + r)) * DD + k0 + c];
        }
        #pragma unroll
        for (int i = 0; i < 4; i++) {
            int lin = tid + 256 * i;
            int r = lin >> 5, c = lin & 31;
            Hs[r][c] = (r < NSTEP) ? g_HW[((size_t)(r * BB) + b) * DD + k0 + c] : 0.f;
        }
        __syncthreads();
        #pragma unroll
        for (int kk = 0; kk < 32; kk++) {
            float ev = Es[nn][kk];
            #pragma unroll
            for (int j = 0; j < 8; j++)
                acc[j] += ev * Hs[tg * 8 + j][kk];
        }
        __syncthreads();
    }
    #pragma unroll
    for (int j = 0; j < 8; j++) {
        int tt = tg * 8 + j;
        if (tt < NSTEP)
            g_scores[((size_t)(tt * BB) + b) * NN + nbase + nn] = acc[j];
    }
}

// softmax + threshold + scatter + eos; grid (31, 32), 256 threads
__global__ void softmax_scatter_kernel(const void* ptrmask,
                                       const int* __restrict__ token_ids,
                                       const int* __restrict__ eosp,
                                       float* __restrict__ out) {
    int t = blockIdx.x, b = blockIdx.y, tid = threadIdx.x;
    __shared__ float sp[NN];
    __shared__ float red[256];
    const float* sc = g_scores + ((size_t)(t * BB) + b) * NN;

    // masked scores + max
    float m = -1e30f;
    for (int n = tid; n < NN; n += 256) {
        bool pm = getmask(ptrmask, b * NN + n);
        float s = pm ? sc[n] : -1e30f;
        sp[n] = s;
        m = fmaxf(m, s);
    }
    red[tid] = m; __syncthreads();
    for (int s = 128; s > 0; s >>= 1) {
        if (tid < s) red[tid] = fmaxf(red[tid], red[tid + s]);
        __syncthreads();
    }
    m = red[0]; __syncthreads();

    // exp + sum
    float lsum = 0.f;
    for (int n = tid; n < NN; n += 256) {
        float s = sp[n];
        float e = (s > -1e29f) ? expf(s - m) : 0.f;
        sp[n] = e;
        lsum += e;
    }
    red[tid] = lsum; __syncthreads();
    for (int s = 128; s > 0; s >>= 1) {
        if (tid < s) red[tid] += red[tid + s];
        __syncthreads();
    }
    float sum = red[0];
    float thr = 1.0f / g_cntptr[b];
    float* orow = out + ((size_t)(t + 1)) * BB * VV + (size_t)b * VV;
    __syncthreads();

    // threshold + scatter
    float ks = 0.f;
    for (int n = tid; n < NN; n += 256) {
        float e = sp[n];
        if (e > 0.f) {
            float p = e / sum;
            if (p >= thr) {
                atomicAdd(&orow[token_ids[b * NN + n]], p);
                ks += p;
            }
        }
    }
    red[tid] = ks; __syncthreads();
    for (int s = 128; s > 0; s >>= 1) {
        if (tid < s) red[tid] += red[tid + s];
        __syncthreads();
    }
    if (tid == 0) {
        __threadfence();
        orow[eosp[0]] = 1.0f - red[0];
    }
}

// ---------------- host launcher ---------------------------------------------
extern "C" void kernel_launch(void* const* d_in, const int* in_sizes, int n_in,
                              void* d_out, int out_size) {
    const float* enc    = (const float*)d_in[0];
    const float* emb    = (const float*)d_in[1];
    const float* W_ih   = (const float*)d_in[2];
    const float* W_hh   = (const float*)d_in[3];
    const float* b_ih   = (const float*)d_in[4];
    const float* b_hh   = (const float*)d_in[5];
    const float* W_att  = (const float*)d_in[6];
    const void*  pad    = d_in[7];
    const void*  ptr    = d_in[8];
    const int*   tokid  = (const int*)d_in[9];
    const int*   target = (const int*)d_in[10];
    const int*   sosp   = (const int*)d_in[11];
    const int*   eosp   = (const int*)d_in[12];
    float* out = (float*)d_out;

    detect_kernel<<<1, 1>>>((const int*)pad);

    int n4 = (TT * BB * VV) / 4;
    zero_kernel<<<4096, 256>>>((float4*)out, n4);
    sos_kernel<<<1, 32>>>(out, sosp);

    counts_kernel<<<BB, 256>>>(pad, ptr);
    {
        dim3 g(2, BB, 4);
        h0part_kernel<<<g, 256>>>(enc, pad);
    }
    h0fin_kernel<<<BB, DD>>>();

    for (int t = 0; t < NSTEP; t++) {
        gates_kernel<<<64, 256>>>(emb, W_ih, W_hh, b_ih, b_hh, target, sosp, t);
        point_kernel<<<BB, DD>>>(t);
    }

    {
        dim3 g(NSTEP, DD / 32);  // (31, 16)
        hw_kernel<<<g, 256>>>(W_att);
    }
    {
        dim3 g(NN / 64, BB);     // (32, 32)
        scores_kernel<<<g, 256>>>(enc);
    }
    {
        dim3 g(NSTEP, BB);       // (31, 32)
        softmax_scatter_kernel<<<g, 256>>>(ptr, tokid, eosp, out);
    }
}

// round 2
// speedup vs baseline: 1.0135x; 1.0135x over previous
#include <cuda_runtime.h>
#include <cuda_bf16.h>
#include <cstdint>

// Problem constants (fixed by setup_inputs)
#define BB 32
#define NN 2048
#define DD 512
#define EE 512
#define VV 32000
#define TT 32          // output_len
#define NSTEP 31       // T-1 decode steps

// ---------------- scratch (device globals; no allocation allowed) -----------
__device__ float g_h[BB * DD];
__device__ float g_c[BB * DD];
__device__ float g_gates[BB * 4 * DD];
__device__ float g_Hall[NSTEP * BB * DD];     // all h_t
__device__ float g_HW[NSTEP * BB * DD];       // h_t @ W_att^T
__device__ float g_scores[NSTEP * BB * NN];   // 8.1 MB
__device__ float g_h0part[4 * BB * DD];
__device__ float g_cntpad[BB];
__device__ float g_cntptr[BB];
__device__ int   g_mask_mode;                 // 0=byte, 1=int32, 2=float32

// ---------------- mask accessor (dtype detected at runtime) -----------------
__device__ __forceinline__ bool getmask(const void* p, int idx) {
    int m = g_mask_mode;
    if (m == 1) return ((const int*)p)[idx] != 0;
    if (m == 2) return ((const float*)p)[idx] != 0.0f;
    return ((const unsigned char*)p)[idx] != 0;
}

__device__ __forceinline__ float sigm(float x) { return 1.0f / (1.0f + expf(-x)); }

// ---------------- kernels ---------------------------------------------------

__global__ void detect_kernel(const int* pad_as_int) {
    int v = pad_as_int[0];
    g_mask_mode = (v == 1) ? 1 : ((v == 0x3F800000) ? 2 : 0);
}

__global__ void zero_kernel(float4* out, int n4) {
    int idx = blockIdx.x * blockDim.x + threadIdx.x;
    int stride = gridDim.x * blockDim.x;
    float4 z = {0.f, 0.f, 0.f, 0.f};
    for (int i = idx; i < n4; i += stride) out[i] = z;
}

__global__ void sos_kernel(float* out, const int* sosp) {
    int b = threadIdx.x;
    if (b < BB) out[(size_t)b * VV + sosp[0]] = 1.0f;
}

__global__ void counts_kernel(const void* pad, const void* ptr) {
    int b = blockIdx.x, tid = threadIdx.x;
    __shared__ int r1[256], r2[256];
    int c1 = 0, c2 = 0;
    for (int n = tid; n < NN; n += 256) {
        c1 += getmask(pad, b * NN + n) ? 1 : 0;
        c2 += getmask(ptr, b * NN + n) ? 1 : 0;
    }
    r1[tid] = c1; r2[tid] = c2; __syncthreads();
    for (int s = 128; s > 0; s >>= 1) {
        if (tid < s) { r1[tid] += r1[tid + s]; r2[tid] += r2[tid + s]; }
        __syncthreads();
    }
    if (tid == 0) { g_cntpad[b] = (float)r1[0]; g_cntptr[b] = (float)r2[0]; }
}

// h0 partial sums: grid (2 d-chunks, B, 4 n-splits), 256 threads
__global__ void h0part_kernel(const float* __restrict__ enc, const void* pad) {
    int dc = blockIdx.x, b = blockIdx.y, z = blockIdx.z;
    int d = dc * 256 + threadIdx.x;
    float acc = 0.0f;
    int n0 = z * (NN / 4);
    for (int n = n0; n < n0 + NN / 4; n++) {
        if (getmask(pad, b * NN + n))
            acc += enc[((size_t)(b * NN + n)) * DD + d];
    }
    g_h0part[((z * BB) + b) * DD + d] = acc;
}

__global__ void h0fin_kernel() {
    int b = blockIdx.x, d = threadIdx.x;  // 512 threads
    float s = 0.0f;
    #pragma unroll
    for (int z = 0; z < 4; z++) s += g_h0part[((z * BB) + b) * DD + d];
    float h = s / g_cntpad[b];
    g_h[b * DD + d] = h;
    g_c[b * DD + d] = h;
}

// gates[b, j] = b_ih[j]+b_hh[j] + x[b]·W_ih[j,:] + h[b]·W_hh[j,:]
// grid 64 blocks (32 gate rows each), 256 threads
__global__ void gates_kernel(const float* __restrict__ emb,
                             const float* __restrict__ W_ih,
                             const float* __restrict__ W_hh,
                             const float* __restrict__ b_ih,
                             const float* __restrict__ b_hh,
                             const int* __restrict__ target,
                             const int* __restrict__ sosp,
                             int t) {
    __shared__ float Ws[32][33];
    __shared__ float Xs[32][33];
    __shared__ int   toks[32];
    int tid = threadIdx.x;
    int jbase = blockIdx.x * 32;
    if (tid < 32) toks[tid] = (t == 0) ? sosp[0] : target[t * BB + tid];
    __syncthreads();
    int tx = tid & 31;   // batch
    int ty = tid >> 5;   // 0..7
    float acc[4];
    #pragma unroll
    for (int i = 0; i < 4; i++) {
        int j = jbase + ty + 8 * i;
        acc[i] = b_ih[j] + b_hh[j];
    }
    for (int phase = 0; phase < 2; phase++) {
        const float* W = phase ? W_hh : W_ih;
        for (int k0 = 0; k0 < 512; k0 += 32) {
            #pragma unroll
            for (int i = 0; i < 4; i++) {
                int lin = tid + 256 * i;
                int r = lin >> 5, c = lin & 31;
                Ws[r][c] = W[(size_t)(jbase + r) * 512 + k0 + c];
                Xs[r][c] = phase ? g_h[r * DD + k0 + c]
                                 : emb[(size_t)toks[r] * EE + k0 + c];
            }
            __syncthreads();
            #pragma unroll
            for (int kk = 0; kk < 32; kk++) {
                float xv = Xs[tx][kk];
                #pragma unroll
                for (int i = 0; i < 4; i++)
                    acc[i] += Ws[ty + 8 * i][kk] * xv;
            }
            __syncthreads();
        }
    }
    #pragma unroll
    for (int i = 0; i < 4; i++)
        g_gates[tx * (4 * DD) + jbase + ty + 8 * i] = acc[i];
}

// pointwise LSTM: grid B, 512 threads
__global__ void point_kernel(int t) {
    int b = blockIdx.x, d = threadIdx.x;
    const float* g = g_gates + b * (4 * DD);
    float gi = g[d], gf = g[DD + d], gg = g[2 * DD + d], go = g[3 * DD + d];
    float c = g_c[b * DD + d];
    float cn = sigm(gf) * c + sigm(gi) * tanhf(gg);
    float hn = sigm(go) * tanhf(cn);
    g_c[b * DD + d] = cn;
    g_h[b * DD + d] = hn;
    g_Hall[((size_t)t * BB + b) * DD + d] = hn;
}

// HW[m, dout] = Hall[m,:] · W_att[dout,:]   (m = t*B+b), grid (31, 16)
__global__ void hw_kernel(const float* __restrict__ Watt) {
    __shared__ float As[32][33], Bs[32][33];
    int tid = threadIdx.x;
    int mbase = blockIdx.x * 32, nbase = blockIdx.y * 32;
    int tx = tid & 31, ty = tid >> 5;
    float acc[4] = {0.f, 0.f, 0.f, 0.f};
    for (int k0 = 0; k0 < 512; k0 += 32) {
        #pragma unroll
        for (int i = 0; i < 4; i++) {
            int lin = tid + 256 * i;
            int r = lin >> 5, c = lin & 31;
            As[r][c] = g_Hall[(size_t)(mbase + r) * DD + k0 + c];
            Bs[r][c] = Watt[(size_t)(nbase + r) * DD + k0 + c];
        }
        __syncthreads();
        #pragma unroll
        for (int kk = 0; kk < 32; kk++) {
            float av = As[tx][kk];
            #pragma unroll
            for (int i = 0; i < 4; i++) acc[i] += Bs[ty + 8 * i][kk] * av;
        }
        __syncthreads();
    }
    #pragma unroll
    for (int i = 0; i < 4; i++)
        g_HW[(size_t)(mbase + tx) * DD + nbase + ty + 8 * i] = acc[i];
}

// scores[t,b,n] = enc[b,n,:] · HW[t*B+b,:]; grid (32 node tiles, 32 b), 256 thr
__global__ void scores_kernel(const float* __restrict__ enc) {
    __shared__ float Es[64][33];
    __shared__ float Hs[32][33];
    int tid = threadIdx.x;
    int nbase = blockIdx.x * 64;
    int b = blockIdx.y;
    int nn = tid & 63, tg = tid >> 6;   // tg: 0..3, 8 t's each
    float acc[8];
    #pragma unroll
    for (int j = 0; j < 8; j++) acc[j] = 0.f;
    for (int k0 = 0; k0 < 512; k0 += 32) {
        #pragma unroll
        for (int i = 0; i < 8; i++) {
            int lin = tid + 256 * i;
            int r = lin >> 5, c = lin & 31;
            Es[r][c] = enc[((size_t)(b * NN + nbase + r)) * DD + k0 + c];
        }
        #pragma unroll
        for (int i = 0; i < 4; i++) {
            int lin = tid + 256 * i;
            int r = lin >> 5, c = lin & 31;
            Hs[r][c] = (r < NSTEP) ? g_HW[((size_t)(r * BB) + b) * DD + k0 + c] : 0.f;
        }
        __syncthreads();
        #pragma unroll
        for (int kk = 0; kk < 32; kk++) {
            float ev = Es[nn][kk];
            #pragma unroll
            for (int j = 0; j < 8; j++)
                acc[j] += ev * Hs[tg * 8 + j][kk];
        }
        __syncthreads();
    }
    #pragma unroll
    for (int j = 0; j < 8; j++) {
        int tt = tg * 8 + j;
        if (tt < NSTEP)
            g_scores[((size_t)(tt * BB) + b) * NN + nbase + nn] = acc[j];
    }
}

// softmax + threshold + scatter + eos; grid (31, 32), 256 threads
__global__ void softmax_scatter_kernel(const void* ptrmask,
                                       const int* __restrict__ token_ids,
                                       const int* __restrict__ eosp,
                                       float* __restrict__ out) {
    int t = blockIdx.x, b = blockIdx.y, tid = threadIdx.x;
    __shared__ float sp[NN];
    __shared__ float red[256];
    const float* sc = g_scores + ((size_t)(t * BB) + b) * NN;

    // masked scores + max
    float m = -1e30f;
    for (int n = tid; n < NN; n += 256) {
        bool pm = getmask(ptrmask, b * NN + n);
        float s = pm ? sc[n] : -1e30f;
        sp[n] = s;
        m = fmaxf(m, s);
    }
    red[tid] = m; __syncthreads();
    for (int s = 128; s > 0; s >>= 1) {
        if (tid < s) red[tid] = fmaxf(red[tid], red[tid + s]);
        __syncthreads();
    }
    m = red[0]; __syncthreads();

    // exp + sum
    float lsum = 0.f;
    for (int n = tid; n < NN; n += 256) {
        float s = sp[n];
        float e = (s > -1e29f) ? expf(s - m) : 0.f;
        sp[n] = e;
        lsum += e;
    }
    red[tid] = lsum; __syncthreads();
    for (int s = 128; s > 0; s >>= 1) {
        if (tid < s) red[tid] += red[tid + s];
        __syncthreads();
    }
    float sum = red[0];
    float thr = 1.0f / g_cntptr[b];
    float* orow = out + ((size_t)(t + 1)) * BB * VV + (size_t)b * VV;
    __syncthreads();

    // threshold + scatter
    float ks = 0.f;
    for (int n = tid; n < NN; n += 256) {
        float e = sp[n];
        if (e > 0.f) {
            float p = e / sum;
            if (p >= thr) {
                atomicAdd(&orow[token_ids[b * NN + n]], p);
                ks += p;
            }
        }
    }
    red[tid] = ks; __syncthreads();
    for (int s = 128; s > 0; s >>= 1) {
        if (tid < s) red[tid] += red[tid + s];
        __syncthreads();
    }
    if (tid == 0) {
        __threadfence();
        orow[eosp[0]] = 1.0f - red[0];
    }
}

// ---------------- host launcher ---------------------------------------------
extern "C" void kernel_launch(void* const* d_in, const int* in_sizes, int n_in,
                              void* d_out, int out_size) {
    const float* enc    = (const float*)d_in[0];
    const float* emb    = (const float*)d_in[1];
    const float* W_ih   = (const float*)d_in[2];
    const float* W_hh   = (const float*)d_in[3];
    const float* b_ih   = (const float*)d_in[4];
    const float* b_hh   = (const float*)d_in[5];
    const float* W_att  = (const float*)d_in[6];
    const void*  pad    = d_in[7];
    const void*  ptr    = d_in[8];
    const int*   tokid  = (const int*)d_in[9];
    const int*   target = (const int*)d_in[10];
    const int*   sosp   = (const int*)d_in[11];
    const int*   eosp   = (const int*)d_in[12];
    float* out = (float*)d_out;

    detect_kernel<<<1, 1>>>((const int*)pad);

    int n4 = (TT * BB * VV) / 4;
    zero_kernel<<<4096, 256>>>((float4*)out, n4);
    sos_kernel<<<1, 32>>>(out, sosp);

    counts_kernel<<<BB, 256>>>(pad, ptr);
    {
        dim3 g(2, BB, 4);
        h0part_kernel<<<g, 256>>>(enc, pad);
    }
    h0fin_kernel<<<BB, DD>>>();

    for (int t = 0; t < NSTEP; t++) {
        gates_kernel<<<64, 256>>>(emb, W_ih, W_hh, b_ih, b_hh, target, sosp, t);
        point_kernel<<<BB, DD>>>(t);
    }

    {
        dim3 g(NSTEP, DD / 32);  // (31, 16)
        hw_kernel<<<g, 256>>>(W_att);
    }
    {
        dim3 g(NN / 64, BB);     // (32, 32)
        scores_kernel<<<g, 256>>>(enc);
    }
    {
        dim3 g(NSTEP, BB);       // (31, 32)
        softmax_scatter_kernel<<<g, 256>>>(ptr, tokid, eosp, out);
    }
}

// round 3
// speedup vs baseline: 3.8984x; 3.8466x over previous
#include <cuda_runtime.h>
#include <cuda_bf16.h>
#include <cstdint>

#define BB 32
#define NN 2048
#define DD 512
#define EE 512
#define VV 32000
#define TT 32
#define NSTEP 31
#define MM (NSTEP * BB)   // 992
#define KSL 8             // k slices for recurrence GEMM
#define KCH 64            // k per slice

typedef unsigned long long ull;

// ---------------- scratch ----------------------------------------------------
__device__ float g_h[BB * DD];
__device__ float g_c[BB * DD];
__device__ float g_Hall[MM * DD];
__device__ float g_HW[MM * DD];
__device__ float g_scores[MM * NN];         // 8.1 MB
__device__ float g_gx[MM * 4 * DD];         // 8.1 MB  (x-side gates + biases)
__device__ float g_gp[KSL * BB * 4 * DD];   // 2 MB    (h-side partials)
__device__ float g_h0part[4 * BB * DD];
__device__ float g_cntpad[BB];
__device__ float g_cntptr[BB];
__device__ int   g_mask_mode;
__device__ unsigned g_barcnt;

// ---------------- helpers -----------------------------------------------------
__device__ __forceinline__ bool getmask(const void* p, int idx) {
    int m = g_mask_mode;
    if (m == 1) return ((const int*)p)[idx] != 0;
    if (m == 2) return ((const float*)p)[idx] != 0.0f;
    return ((const unsigned char*)p)[idx] != 0;
}
__device__ __forceinline__ float sigm(float x) { return 1.0f / (1.0f + expf(-x)); }

__device__ __forceinline__ ull ld2(const float* p) {
    return *(const ull*)p;
}
__device__ __forceinline__ ull fma2(ull a, ull b, ull c) {
    ull d;
    asm("fma.rn.f32x2 %0, %1, %2, %3;" : "=l"(d) : "l"(a), "l"(b), "l"(c));
    return d;
}
__device__ __forceinline__ float sum2(ull v) {
    return __uint_as_float((unsigned)v) + __uint_as_float((unsigned)(v >> 32));
}

// ---------------- setup kernels ----------------------------------------------
__global__ void detect_kernel(const int* pad_as_int) {
    int v = pad_as_int[0];
    g_mask_mode = (v == 1) ? 1 : ((v == 0x3F800000) ? 2 : 0);
    g_barcnt = 0;
}

__global__ void zero_kernel(float4* out, int n4) {
    int idx = blockIdx.x * blockDim.x + threadIdx.x;
    int stride = gridDim.x * blockDim.x;
    float4 z = {0.f, 0.f, 0.f, 0.f};
    for (int i = idx; i < n4; i += stride) out[i] = z;
}

__global__ void sos_kernel(float* out, const int* sosp) {
    int b = threadIdx.x;
    if (b < BB) out[(size_t)b * VV + sosp[0]] = 1.0f;
}

__global__ void counts_kernel(const void* pad, const void* ptr) {
    int b = blockIdx.x, tid = threadIdx.x;
    __shared__ int r1[256], r2[256];
    int c1 = 0, c2 = 0;
    for (int n = tid; n < NN; n += 256) {
        c1 += getmask(pad, b * NN + n) ? 1 : 0;
        c2 += getmask(ptr, b * NN + n) ? 1 : 0;
    }
    r1[tid] = c1; r2[tid] = c2; __syncthreads();
    for (int s = 128; s > 0; s >>= 1) {
        if (tid < s) { r1[tid] += r1[tid + s]; r2[tid] += r2[tid + s]; }
        __syncthreads();
    }
    if (tid == 0) { g_cntpad[b] = (float)r1[0]; g_cntptr[b] = (float)r2[0]; }
}

__global__ void h0part_kernel(const float* __restrict__ enc, const void* pad) {
    int dc = blockIdx.x, b = blockIdx.y, z = blockIdx.z;
    int d = dc * 256 + threadIdx.x;
    float acc = 0.0f;
    int n0 = z * (NN / 4);
    for (int n = n0; n < n0 + NN / 4; n++) {
        if (getmask(pad, b * NN + n))
            acc += enc[((size_t)(b * NN + n)) * DD + d];
    }
    g_h0part[((z * BB) + b) * DD + d] = acc;
}

__global__ void h0fin_kernel() {
    int b = blockIdx.x, d = threadIdx.x;
    float s = 0.0f;
    #pragma unroll
    for (int z = 0; z < 4; z++) s += g_h0part[((z * BB) + b) * DD + d];
    float h = s / g_cntpad[b];
    g_h[b * DD + d] = h;
    g_c[b * DD + d] = h;
}

// ---------------- xgemm: gates_x[m][R] = emb[tok(m)]·W_ih[R] + b_ih + b_hh ---
// grid (16 m-tiles of 64, 32 R-tiles of 64), 256 threads
__global__ void __launch_bounds__(256) xgemm_kernel(
        const float* __restrict__ emb, const float* __restrict__ Wih,
        const float* __restrict__ bih, const float* __restrict__ bhh,
        const int* __restrict__ target, const int* __restrict__ sosp) {
    __shared__ float Xs[64][66];
    __shared__ float Ws[64][66];
    __shared__ int toks[64];
    int tid = threadIdx.x;
    int mbase = blockIdx.x * 64;
    int Rbase = blockIdx.y * 64;
    if (tid < 64) {
        int m = mbase + tid;
        int t = m >> 5, b = m & 31;
        int tok = sosp[0];
        if (m < MM && t > 0) tok = target[t * BB + b];
        toks[tid] = tok;
    }
    int tx = tid & 15;   // R dim: R = Rbase + tx + 16*i
    int ty = tid >> 4;   // m dim: m = mbase + ty*4 + j   (ty 0..15)
    ull acc[4][4] = {};
    for (int k0 = 0; k0 < 512; k0 += 32) {
        __syncthreads();
        #pragma unroll
        for (int i = 0; i < 8; i++) {
            int lin = tid + 256 * i;
            int row = lin >> 5, c = lin & 31;
            Xs[row][c] = emb[(size_t)toks[row] * EE + k0 + c];
            Ws[row][c] = Wih[(size_t)(Rbase + row) * 512 + k0 + c];
        }
        __syncthreads();
        #pragma unroll
        for (int kp = 0; kp < 16; kp++) {
            ull xv[4], wv[4];
            #pragma unroll
            for (int j = 0; j < 4; j++) xv[j] = ld2(&Xs[ty * 4 + j][kp * 2]);
            #pragma unroll
            for (int i = 0; i < 4; i++) wv[i] = ld2(&Ws[tx + 16 * i][kp * 2]);
            #pragma unroll
            for (int i = 0; i < 4; i++)
                #pragma unroll
                for (int j = 0; j < 4; j++)
                    acc[i][j] = fma2(xv[j], wv[i], acc[i][j]);
        }
    }
    #pragma unroll
    for (int j = 0; j < 4; j++) {
        int m = mbase + ty * 4 + j;
        if (m >= MM) continue;
        #pragma unroll
        for (int i = 0; i < 4; i++) {
            int R = Rbase + tx + 16 * i;
            g_gx[((size_t)m << 11) + R] = sum2(acc[i][j]) + bih[R] + bhh[R];
        }
    }
}

// ---------------- grid barrier ------------------------------------------------
__device__ __forceinline__ void gbar(unsigned target) {
    __threadfence();
    __syncthreads();
    if (threadIdx.x == 0) {
        atomicAdd(&g_barcnt, 1u);
        while (atomicAdd(&g_barcnt, 0u) < target) {}
        __threadfence();
    }
    __syncthreads();
}

// ---------------- persistent LSTM recurrence ---------------------------------
// 128 blocks x 256 threads. block = (kslice s, dtile dt).
// Wsm holds W_hh rows {g*512 + dt*32 + dl : g in 0..3, dl in 0..31}, k in slice.
__global__ void __launch_bounds__(256) lstm_persistent(const float* __restrict__ Whh) {
    __shared__ float Wsm[128][66];
    __shared__ float hs[32][66];
    int tid = threadIdx.x;
    int bid = blockIdx.x;
    int s  = bid & 7;
    int dt = bid >> 3;
    int k0 = s * KCH;

    // load W_hh slice once (8192 floats)
    for (int i = tid; i < 128 * KCH; i += 256) {
        int lr = i >> 6, kk = i & 63;
        int R = ((lr >> 5) << 9) + (dt << 5) + (lr & 31);
        Wsm[lr][kk] = Whh[(size_t)R * 512 + k0 + kk];
    }

    // pointwise ownership (one (b,d) per thread for tid<128)
    float creg = 0.f;
    int pd = 0, pb = 0;
    if (tid < 128) {
        int idx = bid * 128 + tid;
        pd = idx & 511; pb = idx >> 9;
        creg = g_c[pb * DD + pd];
    }

    int tx = tid & 31;   // row dim: lr = tx + 32*j  (gate j, d-lane tx)
    int ty = tid >> 5;   // b dim:  b = ty*4 + i
    unsigned bcount = 0;

    for (int t = 0; t < NSTEP; t++) {
        // stage h slice [32 b][64 k]
        for (int i = tid; i < 32 * KCH; i += 256) {
            int b = i >> 6, kk = i & 63;
            hs[b][kk] = g_h[b * DD + k0 + kk];
        }
        __syncthreads();

        ull acc[4][4] = {};
        #pragma unroll 8
        for (int kp = 0; kp < 32; kp++) {
            ull hv[4], wv[4];
            #pragma unroll
            for (int i = 0; i < 4; i++) hv[i] = ld2(&hs[ty * 4 + i][kp * 2]);
            #pragma unroll
            for (int j = 0; j < 4; j++) wv[j] = ld2(&Wsm[tx + 32 * j][kp * 2]);
            #pragma unroll
            for (int i = 0; i < 4; i++)
                #pragma unroll
                for (int j = 0; j < 4; j++)
                    acc[i][j] = fma2(hv[i], wv[j], acc[i][j]);
        }
        // partial store: g_gp[s][b][j*512 + dt*32 + tx]
        #pragma unroll
        for (int i = 0; i < 4; i++) {
            int b = ty * 4 + i;
            #pragma unroll
            for (int j = 0; j < 4; j++)
                g_gp[((s * BB + b) << 11) + (j << 9) + (dt << 5) + tx] = sum2(acc[i][j]);
        }

        bcount++; gbar(bcount * 128);   // partials ready

        if (tid < 128) {
            const float* gx = g_gx + ((size_t)(t * BB + pb) << 11);
            float gi = gx[pd], gf = gx[512 + pd], gg = gx[1024 + pd], go = gx[1536 + pd];
            #pragma unroll
            for (int ss = 0; ss < KSL; ss++) {
                const float* gp = g_gp + ((ss * BB + pb) << 11);
                gi += gp[pd]; gf += gp[512 + pd]; gg += gp[1024 + pd]; go += gp[1536 + pd];
            }
            float cn = sigm(gf) * creg + sigm(gi) * tanhf(gg);
            float hn = sigm(go) * tanhf(cn);
            creg = cn;
            g_h[pb * DD + pd] = hn;
            g_Hall[((size_t)(t * BB + pb) << 9) + pd] = hn;
        }

        bcount++; gbar(bcount * 128);   // h ready
    }
}

// ---------------- hw: HW[m][n] = Hall[m]·W_att[n] ----------------------------
// grid (16 m-tiles, 8 n-tiles), 256 threads
__global__ void __launch_bounds__(256) hw_kernel(const float* __restrict__ Watt) {
    __shared__ float As[64][66];
    __shared__ float Ws[64][66];
    int tid = threadIdx.x;
    int mbase = blockIdx.x * 64;
    int nbase = blockIdx.y * 64;
    int tx = tid & 15;   // n = nbase + tx + 16*i
    int ty = tid >> 4;   // m = mbase + ty*4 + j
    ull acc[4][4] = {};
    for (int k0 = 0; k0 < 512; k0 += 32) {
        __syncthreads();
        #pragma unroll
        for (int i = 0; i < 8; i++) {
            int lin = tid + 256 * i;
            int row = lin >> 5, c = lin & 31;
            int m = mbase + row;
            As[row][c] = (m < MM) ? g_Hall[((size_t)m << 9) + k0 + c] : 0.f;
            Ws[row][c] = Watt[(size_t)(nbase + row) * 512 + k0 + c];
        }
        __syncthreads();
        #pragma unroll
        for (int kp = 0; kp < 16; kp++) {
            ull av[4], wv[4];
            #pragma unroll
            for (int j = 0; j < 4; j++) av[j] = ld2(&As[ty * 4 + j][kp * 2]);
            #pragma unroll
            for (int i = 0; i < 4; i++) wv[i] = ld2(&Ws[tx + 16 * i][kp * 2]);
            #pragma unroll
            for (int i = 0; i < 4; i++)
                #pragma unroll
                for (int j = 0; j < 4; j++)
                    acc[i][j] = fma2(av[j], wv[i], acc[i][j]);
        }
    }
    #pragma unroll
    for (int j = 0; j < 4; j++) {
        int m = mbase + ty * 4 + j;
        if (m >= MM) continue;
        #pragma unroll
        for (int i = 0; i < 4; i++)
            g_HW[((size_t)m << 9) + nbase + tx + 16 * i] = sum2(acc[j][i] * 0 + acc[i][j]);
    }
}

// ---------------- scores[t][b][n] = enc[b][n]·HW[t*B+b] ----------------------
// grid (16 n-tiles of 128, 32 b), 256 threads
__global__ void __launch_bounds__(256) scores_kernel(const float* __restrict__ enc) {
    __shared__ float Es[128][66];
    __shared__ float Hs[32][66];
    int tid = threadIdx.x;
    int nbase = blockIdx.x << 7;
    int b = blockIdx.y;
    int tx = tid & 31;   // n = nbase + tx + 32*i
    int ty = tid >> 5;   // t = ty*4 + j
    ull acc[4][4] = {};
    for (int k0 = 0; k0 < 512; k0 += 32) {
        __syncthreads();
        #pragma unroll
        for (int i = 0; i < 16; i++) {
            int lin = tid + 256 * i;
            int row = lin >> 5, c = lin & 31;
            Es[row][c] = enc[((size_t)(b * NN + nbase + row) << 9) + k0 + c];
        }
        #pragma unroll
        for (int i = 0; i < 4; i++) {
            int lin = tid + 256 * i;
            int row = lin >> 5, c = lin & 31;
            Hs[row][c] = (row < NSTEP) ? g_HW[((size_t)(row * BB + b) << 9) + k0 + c] : 0.f;
        }
        __syncthreads();
        #pragma unroll
        for (int kp = 0; kp < 16; kp++) {
            ull ev[4], hv[4];
            #pragma unroll
            for (int i = 0; i < 4; i++) ev[i] = ld2(&Es[tx + 32 * i][kp * 2]);
            #pragma unroll
            for (int j = 0; j < 4; j++) hv[j] = ld2(&Hs[ty * 4 + j][kp * 2]);
            #pragma unroll
            for (int i = 0; i < 4; i++)
                #pragma unroll
                for (int j = 0; j < 4; j++)
                    acc[i][j] = fma2(ev[i], hv[j], acc[i][j]);
        }
    }
    #pragma unroll
    for (int j = 0; j < 4; j++) {
        int t = ty * 4 + j;
        if (t >= NSTEP) continue;
        #pragma unroll
        for (int i = 0; i < 4; i++)
            g_scores[((size_t)(t * BB + b) << 11) + nbase + tx + 32 * i] = sum2(acc[i][j]);
    }
}

// ---------------- softmax + threshold + scatter + eos ------------------------
__global__ void softmax_scatter_kernel(const void* ptrmask,
                                       const int* __restrict__ token_ids,
                                       const int* __restrict__ eosp,
                                       float* __restrict__ out) {
    int t = blockIdx.x, b = blockIdx.y, tid = threadIdx.x;
    __shared__ float sp[NN];
    __shared__ float red[256];
    const float* sc = g_scores + ((size_t)(t * BB) + b) * NN;

    float m = -1e30f;
    for (int n = tid; n < NN; n += 256) {
        bool pm = getmask(ptrmask, b * NN + n);
        float s = pm ? sc[n] : -1e30f;
        sp[n] = s;
        m = fmaxf(m, s);
    }
    red[tid] = m; __syncthreads();
    for (int s = 128; s > 0; s >>= 1) {
        if (tid < s) red[tid] = fmaxf(red[tid], red[tid + s]);
        __syncthreads();
    }
    m = red[0]; __syncthreads();

    float lsum = 0.f;
    for (int n = tid; n < NN; n += 256) {
        float s = sp[n];
        float e = (s > -1e29f) ? expf(s - m) : 0.f;
        sp[n] = e;
        lsum += e;
    }
    red[tid] = lsum; __syncthreads();
    for (int s = 128; s > 0; s >>= 1) {
        if (tid < s) red[tid] += red[tid + s];
        __syncthreads();
    }
    float sum = red[0];
    float thr = 1.0f / g_cntptr[b];
    float* orow = out + ((size_t)(t + 1)) * BB * VV + (size_t)b * VV;
    __syncthreads();

    float ks = 0.f;
    for (int n = tid; n < NN; n += 256) {
        float e = sp[n];
        if (e > 0.f) {
            float p = e / sum;
            if (p >= thr) {
                atomicAdd(&orow[token_ids[b * NN + n]], p);
                ks += p;
            }
        }
    }
    red[tid] = ks; __syncthreads();
    for (int s = 128; s > 0; s >>= 1) {
        if (tid < s) red[tid] += red[tid + s];
        __syncthreads();
    }
    if (tid == 0) {
        __threadfence();
        orow[eosp[0]] = 1.0f - red[0];
    }
}

// ---------------- host launcher ----------------------------------------------
extern "C" void kernel_launch(void* const* d_in, const int* in_sizes, int n_in,
                              void* d_out, int out_size) {
    const float* enc    = (const float*)d_in[0];
    const float* emb    = (const float*)d_in[1];
    const float* W_ih   = (const float*)d_in[2];
    const float* W_hh   = (const float*)d_in[3];
    const float* b_ih   = (const float*)d_in[4];
    const float* b_hh   = (const float*)d_in[5];
    const float* W_att  = (const float*)d_in[6];
    const void*  pad    = d_in[7];
    const void*  ptr    = d_in[8];
    const int*   tokid  = (const int*)d_in[9];
    const int*   target = (const int*)d_in[10];
    const int*   sosp   = (const int*)d_in[11];
    const int*   eosp   = (const int*)d_in[12];
    float* out = (float*)d_out;

    detect_kernel<<<1, 1>>>((const int*)pad);

    int n4 = (TT * BB * VV) / 4;
    zero_kernel<<<4096, 256>>>((float4*)out, n4);
    sos_kernel<<<1, 32>>>(out, sosp);

    counts_kernel<<<BB, 256>>>(pad, ptr);
    {
        dim3 g(2, BB, 4);
        h0part_kernel<<<g, 256>>>(enc, pad);
    }
    h0fin_kernel<<<BB, DD>>>();

    {
        dim3 g(16, 32);
        xgemm_kernel<<<g, 256>>>(emb, W_ih, b_ih, b_hh, target, sosp);
    }

    lstm_persistent<<<128, 256>>>(W_hh);

    {
        dim3 g(16, 8);
        hw_kernel<<<g, 256>>>(W_att);
    }
    {
        dim3 g(16, BB);
        scores_kernel<<<g, 256>>>(enc);
    }
    {
        dim3 g(NSTEP, BB);
        softmax_scatter_kernel<<<g, 256>>>(ptr, tokid, eosp, out);
    }
}

// round 4
// speedup vs baseline: 4.0102x; 1.0287x over previous
#include <cuda_runtime.h>
#include <cuda_bf16.h>
#include <cstdint>

#define BB 32
#define NN 2048
#define DD 512
#define EE 512
#define VV 32000
#define TT 32
#define NSTEP 31
#define MM (NSTEP * BB)   // 992
#define KSL 8             // k slices for recurrence GEMM
#define KCH 64            // k per slice

typedef unsigned long long ull;

// ---------------- scratch ----------------------------------------------------
__device__ float g_h[BB * DD];
__device__ float g_c[BB * DD];
__device__ float g_Hall[MM * DD];
__device__ float g_HW[MM * DD];
__device__ float g_scores[MM * NN];         // 8.1 MB
__device__ float g_gx[MM * 4 * DD];         // 8.1 MB  (x-side gates + biases)
__device__ float g_gp[KSL * BB * 4 * DD];   // 2 MB    (h-side partials)
__device__ float g_h0part[4 * BB * DD];
__device__ float g_cntpad[BB];
__device__ float g_cntptr[BB];
__device__ int   g_mask_mode;
__device__ unsigned g_arrive;

// ---------------- helpers -----------------------------------------------------
__device__ __forceinline__ bool getmask(const void* p, int idx) {
    int m = g_mask_mode;
    if (m == 1) return ((const int*)p)[idx] != 0;
    if (m == 2) return ((const float*)p)[idx] != 0.0f;
    return ((const unsigned char*)p)[idx] != 0;
}
__device__ __forceinline__ float sigm(float x) { return 1.0f / (1.0f + expf(-x)); }

__device__ __forceinline__ ull ld2(const float* p) { return *(const ull*)p; }
__device__ __forceinline__ ull fma2(ull a, ull b, ull c) {
    ull d;
    asm("fma.rn.f32x2 %0, %1, %2, %3;" : "=l"(d) : "l"(a), "l"(b), "l"(c));
    return d;
}
__device__ __forceinline__ float sum2(ull v) {
    return __uint_as_float((unsigned)v) + __uint_as_float((unsigned)(v >> 32));
}

// ---------------- setup kernels ----------------------------------------------
__global__ void detect_kernel(const int* pad_as_int) {
    int v = pad_as_int[0];
    g_mask_mode = (v == 1) ? 1 : ((v == 0x3F800000) ? 2 : 0);
    g_arrive = 0;
}

__global__ void zero_kernel(float4* out, int n4) {
    int idx = blockIdx.x * blockDim.x + threadIdx.x;
    int stride = gridDim.x * blockDim.x;
    float4 z = {0.f, 0.f, 0.f, 0.f};
    for (int i = idx; i < n4; i += stride) out[i] = z;
}

__global__ void sos_kernel(float* out, const int* sosp) {
    int b = threadIdx.x;
    if (b < BB) out[(size_t)b * VV + sosp[0]] = 1.0f;
}

__global__ void h0part_kernel(const float* __restrict__ enc, const void* pad) {
    int dc = blockIdx.x, b = blockIdx.y, z = blockIdx.z;
    int d = dc * 256 + threadIdx.x;
    float acc = 0.0f;
    int n0 = z * (NN / 4);
    for (int n = n0; n < n0 + NN / 4; n++) {
        if (getmask(pad, b * NN + n))
            acc += enc[((size_t)(b * NN + n)) * DD + d];
    }
    g_h0part[((z * BB) + b) * DD + d] = acc;
}

// counts + h0 finalize fused: grid BB, 256 threads
__global__ void counts_h0fin_kernel(const void* pad, const void* ptr) {
    int b = blockIdx.x, tid = threadIdx.x;
    __shared__ int r1[256], r2[256];
    int c1 = 0, c2 = 0;
    for (int n = tid; n < NN; n += 256) {
        c1 += getmask(pad, b * NN + n) ? 1 : 0;
        c2 += getmask(ptr, b * NN + n) ? 1 : 0;
    }
    r1[tid] = c1; r2[tid] = c2; __syncthreads();
    for (int s = 128; s > 0; s >>= 1) {
        if (tid < s) { r1[tid] += r1[tid + s]; r2[tid] += r2[tid + s]; }
        __syncthreads();
    }
    if (tid == 0) { g_cntpad[b] = (float)r1[0]; g_cntptr[b] = (float)r2[0]; }
    __syncthreads();
    float inv = 1.0f / (float)r1[0];
    #pragma unroll
    for (int q = 0; q < 2; q++) {
        int d = tid + q * 256;
        float s = 0.0f;
        #pragma unroll
        for (int z = 0; z < 4; z++) s += g_h0part[((z * BB) + b) * DD + d];
        float h = s * inv;
        g_h[b * DD + d] = h;
        g_c[b * DD + d] = h;
    }
}

// ---------------- xgemm: gates_x[m][R] = emb[tok(m)]·W_ih[R] + b_ih + b_hh ---
// grid (16 R-tiles of 128, 16 m-tiles of 64), 256 threads, per-thread 8R x 4m
__global__ void __launch_bounds__(256) xgemm_kernel(
        const float* __restrict__ emb, const float* __restrict__ Wih,
        const float* __restrict__ bih, const float* __restrict__ bhh,
        const int* __restrict__ target, const int* __restrict__ sosp) {
    __shared__ float Ws[128][34];
    __shared__ float Xs[64][34];
    __shared__ int toks[64];
    int tid = threadIdx.x;
    int Rbase = blockIdx.x * 128;
    int mbase = blockIdx.y * 64;
    if (tid < 64) {
        int m = mbase + tid;
        int t = m >> 5, b = m & 31;
        int tok = sosp[0];
        if (m < MM && t > 0) tok = target[t * BB + b];
        toks[tid] = tok;
    }
    int rl = tid & 15;    // R = Rbase + rl + 16*i, i<8
    int mg = tid >> 4;    // m = mbase + mg*... no: m = mbase + mg*4+j? mg 0..15 covers 64 m
    ull acc[8][4] = {};
    for (int k0 = 0; k0 < 512; k0 += 32) {
        __syncthreads();
        #pragma unroll
        for (int i = 0; i < 16; i++) {
            int lin = tid + 256 * i;
            int row = lin >> 5, c = lin & 31;
            Ws[row][c] = Wih[(size_t)(Rbase + row) * 512 + k0 + c];
        }
        #pragma unroll
        for (int i = 0; i < 8; i++) {
            int lin = tid + 256 * i;
            int row = lin >> 5, c = lin & 31;
            Xs[row][c] = emb[(size_t)toks[row] * EE + k0 + c];
        }
        __syncthreads();
        #pragma unroll
        for (int kp = 0; kp < 16; kp++) {
            ull wv[8], xv[4];
            #pragma unroll
            for (int i = 0; i < 8; i++) wv[i] = ld2(&Ws[rl + 16 * i][kp * 2]);
            #pragma unroll
            for (int j = 0; j < 4; j++) xv[j] = ld2(&Xs[(mg & 15) * 4 + j][kp * 2]);
            #pragma unroll
            for (int i = 0; i < 8; i++)
                #pragma unroll
                for (int j = 0; j < 4; j++)
                    acc[i][j] = fma2(wv[i], xv[j], acc[i][j]);
        }
    }
    #pragma unroll
    for (int j = 0; j < 4; j++) {
        int m = mbase + mg * 4 + j;
        if (m >= MM) continue;
        #pragma unroll
        for (int i = 0; i < 8; i++) {
            int R = Rbase + rl + 16 * i;
            g_gx[((size_t)m << 11) + R] = sum2(acc[i][j]) + bih[R] + bhh[R];
        }
    }
}

// ---------------- grid barrier (release arrive, acquire poll) ----------------
__device__ __forceinline__ void gbar(unsigned target) {
    __syncthreads();
    if (threadIdx.x == 0) {
        asm volatile("red.release.gpu.global.add.u32 [%0], 1;"
                     :: "l"(&g_arrive) : "memory");
        unsigned v;
        do {
            asm volatile("ld.acquire.gpu.global.u32 %0, [%1];"
                         : "=r"(v) : "l"(&g_arrive) : "memory");
        } while (v < target);
    }
    __syncthreads();
}

// ---------------- persistent LSTM recurrence ---------------------------------
// 128 blocks x 256 threads. block = (kslice s, dtile dt).
__global__ void __launch_bounds__(256) lstm_persistent(const float* __restrict__ Whh) {
    __shared__ float Wsm[128][66];
    __shared__ float hs[32][66];
    int tid = threadIdx.x;
    int bid = blockIdx.x;
    int s  = bid & 7;
    int dt = bid >> 3;
    int k0 = s * KCH;

    for (int i = tid; i < 128 * KCH; i += 256) {
        int lr = i >> 6, kk = i & 63;
        int R = ((lr >> 5) << 9) + (dt << 5) + (lr & 31);
        Wsm[lr][kk] = Whh[(size_t)R * 512 + k0 + kk];
    }

    float creg = 0.f;
    int pd = 0, pb = 0;
    if (tid < 128) {
        int idx = bid * 128 + tid;
        pd = idx & 511; pb = idx >> 9;
        creg = g_c[pb * DD + pd];
    }

    int tx = tid & 31;   // lr = tx + 32*j
    int ty = tid >> 5;   // b = ty*4 + i
    unsigned bcount = 0;

    for (int t = 0; t < NSTEP; t++) {
        for (int i = tid; i < 32 * KCH; i += 256) {
            int b = i >> 6, kk = i & 63;
            hs[b][kk] = g_h[b * DD + k0 + kk];
        }
        __syncthreads();

        ull acc[4][4] = {};
        #pragma unroll 8
        for (int kp = 0; kp < 32; kp++) {
            ull hv[4], wv[4];
            #pragma unroll
            for (int i = 0; i < 4; i++) hv[i] = ld2(&hs[ty * 4 + i][kp * 2]);
            #pragma unroll
            for (int j = 0; j < 4; j++) wv[j] = ld2(&Wsm[tx + 32 * j][kp * 2]);
            #pragma unroll
            for (int i = 0; i < 4; i++)
                #pragma unroll
                for (int j = 0; j < 4; j++)
                    acc[i][j] = fma2(hv[i], wv[j], acc[i][j]);
        }
        #pragma unroll
        for (int i = 0; i < 4; i++) {
            int b = ty * 4 + i;
            #pragma unroll
            for (int j = 0; j < 4; j++)
                g_gp[((s * BB + b) << 11) + (j << 9) + (dt << 5) + tx] = sum2(acc[i][j]);
        }

        bcount++; gbar(bcount * 128);   // partials ready

        if (tid < 128) {
            const float* gx = g_gx + ((size_t)(t * BB + pb) << 11);
            float gi = gx[pd], gf = gx[512 + pd], gg = gx[1024 + pd], go = gx[1536 + pd];
            #pragma unroll
            for (int ss = 0; ss < KSL; ss++) {
                const float* gp = g_gp + ((ss * BB + pb) << 11);
                gi += gp[pd]; gf += gp[512 + pd]; gg += gp[1024 + pd]; go += gp[1536 + pd];
            }
            float cn = sigm(gf) * creg + sigm(gi) * tanhf(gg);
            float hn = sigm(go) * tanhf(cn);
            creg = cn;
            g_h[pb * DD + pd] = hn;
            g_Hall[((size_t)(t * BB + pb) << 9) + pd] = hn;
        }

        bcount++; gbar(bcount * 128);   // h ready
    }
}

// ---------------- hw: HW[m][n] = Hall[m]·W_att[n] ----------------------------
__global__ void __launch_bounds__(256) hw_kernel(const float* __restrict__ Watt) {
    __shared__ float As[64][66];
    __shared__ float Ws[64][66];
    int tid = threadIdx.x;
    int mbase = blockIdx.x * 64;
    int nbase = blockIdx.y * 64;
    int tx = tid & 15;
    int ty = tid >> 4;
    ull acc[4][4] = {};
    for (int k0 = 0; k0 < 512; k0 += 32) {
        __syncthreads();
        #pragma unroll
        for (int i = 0; i < 8; i++) {
            int lin = tid + 256 * i;
            int row = lin >> 5, c = lin & 31;
            int m = mbase + row;
            As[row][c] = (m < MM) ? g_Hall[((size_t)m << 9) + k0 + c] : 0.f;
            Ws[row][c] = Watt[(size_t)(nbase + row) * 512 + k0 + c];
        }
        __syncthreads();
        #pragma unroll
        for (int kp = 0; kp < 16; kp++) {
            ull av[4], wv[4];
            #pragma unroll
            for (int j = 0; j < 4; j++) av[j] = ld2(&As[ty * 4 + j][kp * 2]);
            #pragma unroll
            for (int i = 0; i < 4; i++) wv[i] = ld2(&Ws[tx + 16 * i][kp * 2]);
            #pragma unroll
            for (int i = 0; i < 4; i++)
                #pragma unroll
                for (int j = 0; j < 4; j++)
                    acc[i][j] = fma2(av[j], wv[i], acc[i][j]);
        }
    }
    #pragma unroll
    for (int j = 0; j < 4; j++) {
        int m = mbase + ty * 4 + j;
        if (m >= MM) continue;
        #pragma unroll
        for (int i = 0; i < 4; i++)
            g_HW[((size_t)m << 9) + nbase + tx + 16 * i] = sum2(acc[i][j]);
    }
}

// ---------------- scores[t][b][n] = enc[b][n]·HW[t*B+b] ----------------------
// grid (8 n-tiles of 256, 32 b), 256 threads, per-thread 8n x 4t
__global__ void __launch_bounds__(256) scores_kernel(const float* __restrict__ enc) {
    __shared__ float Es[256][34];
    __shared__ float Hs[32][34];
    int tid = threadIdx.x;
    int nbase = blockIdx.x << 8;
    int b = blockIdx.y;
    int nl = tid & 31;   // n = nbase + nl + 32*i, i<8
    int tg = tid >> 5;   // t = tg*4 + j
    ull acc[8][4] = {};
    for (int k0 = 0; k0 < 512; k0 += 32) {
        __syncthreads();
        #pragma unroll
        for (int i = 0; i < 32; i++) {
            int lin = tid + 256 * i;
            int row = lin >> 5, c = lin & 31;
            Es[row][c] = enc[((size_t)(b * NN + nbase + row) << 9) + k0 + c];
        }
        #pragma unroll
        for (int i = 0; i < 4; i++) {
            int lin = tid + 256 * i;
            int row = lin >> 5, c = lin & 31;
            Hs[row][c] = (row < NSTEP) ? g_HW[((size_t)(row * BB + b) << 9) + k0 + c] : 0.f;
        }
        __syncthreads();
        #pragma unroll
        for (int kp = 0; kp < 16; kp++) {
            ull ev[8], hv[4];
            #pragma unroll
            for (int i = 0; i < 8; i++) ev[i] = ld2(&Es[nl + 32 * i][kp * 2]);
            #pragma unroll
            for (int j = 0; j < 4; j++) hv[j] = ld2(&Hs[tg * 4 + j][kp * 2]);
            #pragma unroll
            for (int i = 0; i < 8; i++)
                #pragma unroll
                for (int j = 0; j < 4; j++)
                    acc[i][j] = fma2(ev[i], hv[j], acc[i][j]);
        }
    }
    #pragma unroll
    for (int j = 0; j < 4; j++) {
        int t = tg * 4 + j;
        if (t >= NSTEP) continue;
        #pragma unroll
        for (int i = 0; i < 8; i++)
            g_scores[((size_t)(t * BB + b) << 11) + nbase + nl + 32 * i] = sum2(acc[i][j]);
    }
}

// ---------------- softmax + threshold + scatter + eos ------------------------
__global__ void softmax_scatter_kernel(const void* ptrmask,
                                       const int* __restrict__ token_ids,
                                       const int* __restrict__ eosp,
                                       float* __restrict__ out) {
    int t = blockIdx.x, b = blockIdx.y, tid = threadIdx.x;
    __shared__ float sp[NN];
    __shared__ float red[256];
    const float* sc = g_scores + ((size_t)(t * BB) + b) * NN;

    float m = -1e30f;
    for (int n = tid; n < NN; n += 256) {
        bool pm = getmask(ptrmask, b * NN + n);
        float s = pm ? sc[n] : -1e30f;
        sp[n] = s;
        m = fmaxf(m, s);
    }
    red[tid] = m; __syncthreads();
    for (int s = 128; s > 0; s >>= 1) {
        if (tid < s) red[tid] = fmaxf(red[tid], red[tid + s]);
        __syncthreads();
    }
    m = red[0]; __syncthreads();

    float lsum = 0.f;
    for (int n = tid; n < NN; n += 256) {
        float s = sp[n];
        float e = (s > -1e29f) ? expf(s - m) : 0.f;
        sp[n] = e;
        lsum += e;
    }
    red[tid] = lsum; __syncthreads();
    for (int s = 128; s > 0; s >>= 1) {
        if (tid < s) red[tid] += red[tid + s];
        __syncthreads();
    }
    float sum = red[0];
    float thr = 1.0f / g_cntptr[b];
    float* orow = out + ((size_t)(t + 1)) * BB * VV + (size_t)b * VV;
    __syncthreads();

    float ks = 0.f;
    for (int n = tid; n < NN; n += 256) {
        float e = sp[n];
        if (e > 0.f) {
            float p = e / sum;
            if (p >= thr) {
                atomicAdd(&orow[token_ids[b * NN + n]], p);
                ks += p;
            }
        }
    }
    red[tid] = ks; __syncthreads();
    for (int s = 128; s > 0; s >>= 1) {
        if (tid < s) red[tid] += red[tid + s];
        __syncthreads();
    }
    if (tid == 0) {
        __threadfence();
        orow[eosp[0]] = 1.0f - red[0];
    }
}

// ---------------- host launcher ----------------------------------------------
extern "C" void kernel_launch(void* const* d_in, const int* in_sizes, int n_in,
                              void* d_out, int out_size) {
    const float* enc    = (const float*)d_in[0];
    const float* emb    = (const float*)d_in[1];
    const float* W_ih   = (const float*)d_in[2];
    const float* W_hh   = (const float*)d_in[3];
    const float* b_ih   = (const float*)d_in[4];
    const float* b_hh   = (const float*)d_in[5];
    const float* W_att  = (const float*)d_in[6];
    const void*  pad    = d_in[7];
    const void*  ptr    = d_in[8];
    const int*   tokid  = (const int*)d_in[9];
    const int*   target = (const int*)d_in[10];
    const int*   sosp   = (const int*)d_in[11];
    const int*   eosp   = (const int*)d_in[12];
    float* out = (float*)d_out;

    detect_kernel<<<1, 1>>>((const int*)pad);

    int n4 = (TT * BB * VV) / 4;
    zero_kernel<<<4096, 256>>>((float4*)out, n4);
    sos_kernel<<<1, 32>>>(out, sosp);

    {
        dim3 g(16, 16);
        xgemm_kernel<<<g, 256>>>(emb, W_ih, b_ih, b_hh, target, sosp);
    }
    {
        dim3 g(2, BB, 4);
        h0part_kernel<<<g, 256>>>(enc, pad);
    }
    counts_h0fin_kernel<<<BB, 256>>>(pad, ptr);

    lstm_persistent<<<128, 256>>>(W_hh);

    {
        dim3 g(16, 8);
        hw_kernel<<<g, 256>>>(W_att);
    }
    {
        dim3 g(8, BB);
        scores_kernel<<<g, 256>>>(enc);
    }
    {
        dim3 g(NSTEP, BB);
        softmax_scatter_kernel<<<g, 256>>>(ptr, tokid, eosp, out);
    }
}